// round 3
// baseline (speedup 1.0000x reference)
#include <cuda_runtime.h>
#include <cstdint>

// Log-signature depth 3, d=8, L=256, B=2048.
// Layout: 16 lanes per batch element (2 batches per warp).
//   lane s (0..15): owns i = s>>1, j in {jb..jb+3} with jb = (s&1)*4
//                   -> 4 (i,j) pairs, S2r[4], S3r[4][8] in registers.
//   distributed channel c = s&7: lane keeps dx_c and S1_c as scalars; the
//   full dx vector is materialized per step with 8 shfl broadcasts.
// Scan update (old S1, S2 on RHS):
//   m      = S2[i,j] + (0.5*S1_i + dx_i/6) * dx_j
//   S3    += m * dx_k          (8 FMAs per pair)
//   S2    += (S1_i + 0.5*dx_i) * dx_j
//   S1    += dx
// Epilogue (log in tensor algebra, truncated at 3):
//   l1 = S1
//   l2 = S2 - 0.5 S1_i S1_j
//   l3 = S3 - 0.5 (S1_i S2[j,k] + S2[i,j] S1_k) + (1/3) S1_i S1_j S1_k

#define BATCH   2048
#define LPATH   256
#define DCH     8
#define OUT_PB  584            // 8 + 64 + 512
#define TPB     128            // 4 warps -> 8 batches per block
#define BATCH_PER_BLOCK 8

__global__ __launch_bounds__(TPB)
void logsig_kernel(const float* __restrict__ x, float* __restrict__ out)
{
    const unsigned FULL = 0xffffffffu;
    const int lane  = threadIdx.x & 31;
    const int warp  = threadIdx.x >> 5;
    const int g     = (lane >> 4) & 1;      // group within warp
    const int s     = lane & 15;            // sub-lane within group
    const int c     = s & 7;                // owned channel (distributed dims)
    const int i     = s >> 1;               // owned i (0..7)
    const bool hi   = (s & 1);              // jb = hi ? 4 : 0
    const int base  = lane & 16;            // group base lane in warp
    const int srcI  = base + i;             // shuffle source for channel i

    const int bLocal = warp * 2 + g;
    const long b = (long)blockIdx.x * BATCH_PER_BLOCK + bLocal;

    const float* xb = x + (size_t)b * (LPATH * DCH) + c;

    float S1l = 0.0f;                 // S1[c], distributed
    float S2r[4] = {0.f, 0.f, 0.f, 0.f};
    float S3r[4][8];
#pragma unroll
    for (int q = 0; q < 4; ++q)
#pragma unroll
        for (int k = 0; k < 8; ++k) S3r[q][k] = 0.0f;

    float xl = __ldg(xb);             // x at t=0, own channel

#pragma unroll 4
    for (int t = 1; t < LPATH; ++t) {
        float y   = __ldg(xb + t * DCH);
        float dxl = y - xl;
        xl = y;

        // old-state scalars needed before S1 update
        float S1i = __shfl_sync(FULL, S1l, srcI);
        float dxi = __shfl_sync(FULL, dxl, srcI);

        // full dx vector (group-local broadcast)
        float dxk[8];
#pragma unroll
        for (int k = 0; k < 8; ++k)
            dxk[k] = __shfl_sync(FULL, dxl, base + k);

        S1l += dxl;                   // S1 update (after old S1_i captured)

        float a  = fmaf(dxi, 1.0f / 6.0f, 0.5f * S1i);  // S3 coefficient
        float bb = fmaf(dxi, 0.5f, S1i);                // S2 coefficient

#pragma unroll
        for (int q = 0; q < 4; ++q) {
            float dxj = hi ? dxk[4 + q] : dxk[q];
            float m   = fmaf(a, dxj, S2r[q]);           // uses old S2
            S2r[q]    = fmaf(bb, dxj, S2r[q]);
#pragma unroll
            for (int k = 0; k < 8; ++k)
                S3r[q][k] = fmaf(m, dxk[k], S3r[q][k]);
        }
    }

    // ---------------- epilogue: log projection + writeback ----------------
    __shared__ float s2sh[BATCH_PER_BLOCK][64];

    // publish S2 rows for cross-lane access (needed for S2[j,k])
#pragma unroll
    for (int q = 0; q < 4; ++q)
        s2sh[bLocal][i * 8 + (hi ? 4 : 0) + q] = S2r[q];

    // full S1 vector
    float S1k[8];
#pragma unroll
    for (int k = 0; k < 8; ++k)
        S1k[k] = __shfl_sync(FULL, S1l, base + k);
    float S1i = __shfl_sync(FULL, S1l, srcI);

    __syncwarp(FULL);   // groups are intra-warp; warp sync orders smem

    float* ob = out + (size_t)b * OUT_PB;

    // l1
    if (s < 8) ob[s] = S1l;

    // l2: lane writes 4 consecutive entries at offset 8 + 4*s (16B aligned)
    {
        float4 v;
        float* vv = &v.x;
#pragma unroll
        for (int q = 0; q < 4; ++q) {
            float S1j = hi ? S1k[4 + q] : S1k[q];
            vv[q] = S2r[q] - 0.5f * S1i * S1j;
        }
        *reinterpret_cast<float4*>(ob + 8 + 4 * s) = v;
    }

    // l3: lane writes 32 consecutive entries at offset 72 + 32*s
#pragma unroll
    for (int q = 0; q < 4; ++q) {
        float S1j  = hi ? S1k[4 + q] : S1k[q];
        float S2ij = S2r[q];
        float tij  = (1.0f / 3.0f) * S1i * S1j;
        const float* row = &s2sh[bLocal][(hi ? 4 : 0) * 8 + q * 8]; // (jb+q)*8
        // note: (jb+q)*8 = ((hi?4:0)+q)*8
        float4 lo, hi4;
        float* lv = &lo.x;
        float* hv = &hi4.x;
#pragma unroll
        for (int k = 0; k < 8; ++k) {
            float S2jk = row[k];
            float val  = S3r[q][k]
                       - 0.5f * (S1i * S2jk + S2ij * S1k[k])
                       + tij * S1k[k];
            if (k < 4) lv[k] = val; else hv[k - 4] = val;
        }
        float* dst = ob + 72 + 32 * s + 8 * q;
        *reinterpret_cast<float4*>(dst)     = lo;
        *reinterpret_cast<float4*>(dst + 4) = hi4;
    }
}

extern "C" void kernel_launch(void* const* d_in, const int* in_sizes, int n_in,
                              void* d_out, int out_size)
{
    const float* x = (const float*)d_in[0];
    float* out = (float*)d_out;
    (void)in_sizes; (void)n_in; (void)out_size;

    const int blocks = BATCH / BATCH_PER_BLOCK;   // 256
    logsig_kernel<<<blocks, TPB>>>(x, out);
}

// round 4
// speedup vs baseline: 1.0417x; 1.0417x over previous
#include <cuda_runtime.h>
#include <cstdint>

// Log-signature depth 3, d=8, L=256, B=2048 — chunked scan + Chen composition.
//
// Each batch handled by 4 groups of 16 lanes (4 chunks of the path scanned in
// parallel), then tree-combined with Chen's identity:
//   S1 = S1a + S1b
//   S2[i,j]   = S2a + S1a_i S1b_j + S2b
//   S3[i,j,k] = S3a + S2a[i,j] S1b_k + S1a_i S2b[j,k] + S3b
//
// Lane layout within a 16-lane group: lane s owns i = s>>1, j in {jb..jb+3},
// jb = (s&1)*4 -> S2r[4], S3r[4][8] in registers. Distributed channel c = s&7
// holds dx_c / S1_c; full dx vector materialized via 8 shfls per step.
// S1_i is maintained as a local accumulator (no extra shfl per step).

#define BATCH   2048
#define LPATH   256
#define DCH     8
#define OUT_PB  584
#define TPB     256            // 8 warps = 16 groups = 4 batches x 4 chunks
#define BPB     4
#define SIGSZ   656            // 8 (S1) + 72 (S2, 8 rows x stride 9) + 576 (S3, 64 rows x stride 9)

__global__ __launch_bounds__(TPB)
void logsig_kernel(const float* __restrict__ x, float* __restrict__ out)
{
    const unsigned FULL = 0xffffffffu;
    const int tid  = threadIdx.x;
    const int lane = tid & 31;
    const int s    = lane & 15;
    const int c    = s & 7;           // owned channel
    const int i    = s >> 1;          // owned i
    const bool hib = (s & 1) != 0;
    const int jb   = hib ? 4 : 0;
    const int base = lane & 16;       // group base lane within warp
    const int srcI = base + i;
    const unsigned gmask = 0xFFFFu << base;

    const int gid   = tid >> 4;       // 0..15
    const int bL    = gid >> 2;       // batch within block
    const int chunk = gid & 3;        // chunk index
    const long b = (long)blockIdx.x * BPB + bL;

    const int start = chunk * 64;
    const int nstep = (chunk == 3) ? 63 : 64;    // chunk 3 pads one dx=0 step
    const float* xb = x + ((size_t)b * LPATH + start) * DCH + c;

    float S1l = 0.0f;                 // S1[c] (distributed)
    float S1i = 0.0f;                 // S1[i] (locally accumulated)
    float S2r[4] = {0.f, 0.f, 0.f, 0.f};
    float S3r[4][8];
#pragma unroll
    for (int q = 0; q < 4; ++q)
#pragma unroll
        for (int k = 0; k < 8; ++k) S3r[q][k] = 0.0f;

    float xl = __ldg(xb);

#pragma unroll 4
    for (int t = 1; t <= 64; ++t) {
        float y   = (t <= nstep) ? __ldg(xb + t * DCH) : xl;  // dx=0 pad = identity
        float dxl = y - xl;
        xl = y;

        float dxi = __shfl_sync(FULL, dxl, srcI);
        float dxk[8];
#pragma unroll
        for (int k = 0; k < 8; ++k)
            dxk[k] = __shfl_sync(FULL, dxl, base + k);

        float a  = fmaf(dxi, 1.0f / 6.0f, 0.5f * S1i);   // old S1i
        float bb = fmaf(dxi, 0.5f, S1i);
        S1l += dxl;
        S1i += dxi;

#pragma unroll
        for (int q = 0; q < 4; ++q) {
            float dxj = hib ? dxk[4 + q] : dxk[q];
            float m   = fmaf(a, dxj, S2r[q]);            // old S2
            S2r[q]    = fmaf(bb, dxj, S2r[q]);
#pragma unroll
            for (int k = 0; k < 8; ++k)
                S3r[q][k] = fmaf(m, dxk[k], S3r[q][k]);
        }
    }

    // ---------------- Chen tree-combine via shared memory ----------------
    __shared__ float sig[BPB][4][SIGSZ];

    auto store_sig = [&](float* p) {
        if (s < 8) p[s] = S1l;
#pragma unroll
        for (int q = 0; q < 4; ++q)
            p[8 + i * 9 + jb + q] = S2r[q];
#pragma unroll
        for (int q = 0; q < 4; ++q)
#pragma unroll
            for (int k = 0; k < 8; ++k)
                p[80 + (i * 8 + jb + q) * 9 + k] = S3r[q][k];
    };

    auto combine = [&](const float* p) {   // regs = a (earlier), p = b (later)
        float S1b[8];
#pragma unroll
        for (int k = 0; k < 8; ++k) S1b[k] = p[k];
#pragma unroll
        for (int q = 0; q < 4; ++q) {
            const int j = jb + q;
            const float* s2row = p + 8 + j * 9;              // S2b[j,:]
            const float* s3row = p + 80 + (i * 8 + j) * 9;   // S3b[i,j,:]
#pragma unroll
            for (int k = 0; k < 8; ++k)
                S3r[q][k] += S2r[q] * S1b[k] + S1i * s2row[k] + s3row[k];
            float S1bj = hib ? S1b[4 + q] : S1b[q];
            S2r[q] += S1i * S1bj + p[8 + i * 9 + j];
        }
        S1l += p[c];
        S1i += p[i];
    };

    if (chunk == 1 || chunk == 3) store_sig(&sig[bL][chunk][0]);
    __syncthreads();
    if (chunk == 0) {
        combine(&sig[bL][1][0]);
    } else if (chunk == 2) {
        combine(&sig[bL][3][0]);
        store_sig(&sig[bL][2][0]);
    }
    __syncthreads();
    if (chunk != 0) return;

    combine(&sig[bL][2][0]);

    // ---------------- log projection + writeback (chunk-0 groups) --------
    float* p0 = &sig[bL][0][0];
#pragma unroll
    for (int q = 0; q < 4; ++q)
        p0[8 + i * 9 + jb + q] = S2r[q];       // publish full S2 for [j,k] reads

    float S1k[8];
#pragma unroll
    for (int k = 0; k < 8; ++k)
        S1k[k] = __shfl_sync(gmask, S1l, base + k);
    __syncwarp(gmask);

    float* ob = out + (size_t)b * OUT_PB;

    // l1
    if (s < 8) ob[s] = S1l;

    // l2 = S2 - 0.5 S1 x S1
    {
        float4 v; float* vv = &v.x;
#pragma unroll
        for (int q = 0; q < 4; ++q) {
            float S1j = hib ? S1k[4 + q] : S1k[q];
            vv[q] = S2r[q] - 0.5f * S1i * S1j;
        }
        *reinterpret_cast<float4*>(ob + 8 + 4 * s) = v;
    }

    // l3 = S3 - 0.5 (S1_i S2[j,k] + S2[i,j] S1_k) + (1/3) S1_i S1_j S1_k
#pragma unroll
    for (int q = 0; q < 4; ++q) {
        float S1j  = hib ? S1k[4 + q] : S1k[q];
        float S2ij = S2r[q];
        float tij  = (1.0f / 3.0f) * S1i * S1j;
        const float* row = p0 + 8 + (jb + q) * 9;    // S2[j,:]
        float4 lo, hi4;
        float* lv = &lo.x; float* hv = &hi4.x;
#pragma unroll
        for (int k = 0; k < 8; ++k) {
            float val = S3r[q][k]
                      - 0.5f * (S1i * row[k] + S2ij * S1k[k])
                      + tij * S1k[k];
            if (k < 4) lv[k] = val; else hv[k - 4] = val;
        }
        float* dst = ob + 72 + 32 * s + 8 * q;
        *reinterpret_cast<float4*>(dst)     = lo;
        *reinterpret_cast<float4*>(dst + 4) = hi4;
    }
}

extern "C" void kernel_launch(void* const* d_in, const int* in_sizes, int n_in,
                              void* d_out, int out_size)
{
    const float* x = (const float*)d_in[0];
    float* out = (float*)d_out;
    (void)in_sizes; (void)n_in; (void)out_size;

    const int blocks = BATCH / BPB;   // 512
    logsig_kernel<<<blocks, TPB>>>(x, out);
}

// round 5
// speedup vs baseline: 1.1691x; 1.1223x over previous
#include <cuda_runtime.h>
#include <cstdint>

// Log-signature depth 3, d=8, L=256, B=2048.
// Chunked scan (4 chunks/path, Chen tree-combine) + packed f32x2 inner loop.
//
// Every lane loads the FULL 8-channel x vector per step (two LDG.128 ->
// four packed f32x2 regs; pure L1 broadcast within the 16-lane group), so
// the scan has ZERO shuffles. Lane s of a group owns i = s>>1 and
// j in {jb..jb+3}, jb=(s&1)*4: S2 as 2 f32x2, S3 as 16 f32x2.
// Per step (old state on RHS):
//   m_q  = S2[i,j] + (0.5*S1_i + dx_i/6) * dx_j
//   S3  += m_q (x) dx          (16 fma.rn.f32x2)
//   S2  += (S1_i + 0.5*dx_i) * dx_j
// S1 is never scanned: S1 = x_end - x_start (computed once); only the
// scalar S1_i is kept incrementally for the coefficients.

#define BATCH   2048
#define LPATH   256
#define DCH     8
#define OUT_PB  584
#define TPB     256            // 16 groups = 4 batches x 4 chunks
#define BPB     4
#define SIGSZ   656            // 8 + 8x9 (S2) + 64x9 (S3)

using u64 = unsigned long long;

__device__ __forceinline__ u64 pack2(float lo, float hi) {
    u64 r; asm("mov.b64 %0, {%1, %2};" : "=l"(r) : "f"(lo), "f"(hi)); return r;
}
__device__ __forceinline__ void unpack2(u64 v, float& lo, float& hi) {
    asm("mov.b64 {%0, %1}, %2;" : "=f"(lo), "=f"(hi) : "l"(v));
}
__device__ __forceinline__ u64 fma2(u64 a, u64 b, u64 c) {
    u64 d; asm("fma.rn.f32x2 %0, %1, %2, %3;" : "=l"(d) : "l"(a), "l"(b), "l"(c)); return d;
}

__global__ __launch_bounds__(TPB)
void logsig_kernel(const float* __restrict__ x, float* __restrict__ out)
{
    const int tid  = threadIdx.x;
    const int lane = tid & 31;
    const int s    = lane & 15;
    const int i    = s >> 1;
    const bool hib = (s & 1) != 0;
    const int jb   = hib ? 4 : 0;

    const int gid   = tid >> 4;
    const int bL    = gid >> 2;
    const int chunk = gid & 3;
    const long b = (long)blockIdx.x * BPB + bL;

    const int start = chunk * 64;
    const int nstep = (chunk == 3) ? 63 : 64;   // last step of chunk 3 is a dx=0 pad
    const float* xf = x + ((size_t)b * LPATH + start) * DCH;
    const longlong2* xv = reinterpret_cast<const longlong2*>(xf);

    const u64 NEG1 = pack2(-1.0f, -1.0f);

    u64 S3p[4][4];
#pragma unroll
    for (int q = 0; q < 4; ++q)
#pragma unroll
        for (int kp = 0; kp < 4; ++kp) S3p[q][kp] = 0ull;
    u64 S2p0 = 0ull, S2p1 = 0ull;
    float S1i = 0.0f;

    longlong2 v0 = __ldg(xv);
    longlong2 v1 = __ldg(xv + 1);
    u64 xp0 = (u64)v0.x, xp1 = (u64)v0.y, xp2 = (u64)v1.x, xp3 = (u64)v1.y;
    const u64 x00 = xp0, x01 = xp1, x02 = xp2, x03 = xp3;
    float xli = __ldg(xf + i);

#pragma unroll 4
    for (int t = 1; t <= 64; ++t) {
        const int tt = (t <= nstep) ? t : nstep;   // pad reloads last point -> dx = 0
        longlong2 va = __ldg(xv + 2 * tt);
        longlong2 vb = __ldg(xv + 2 * tt + 1);
        float yi = __ldg(xf + (size_t)tt * DCH + i);

        u64 d0 = fma2(xp0, NEG1, (u64)va.x);
        u64 d1 = fma2(xp1, NEG1, (u64)va.y);
        u64 d2 = fma2(xp2, NEG1, (u64)vb.x);
        u64 d3 = fma2(xp3, NEG1, (u64)vb.y);
        xp0 = (u64)va.x; xp1 = (u64)va.y; xp2 = (u64)vb.x; xp3 = (u64)vb.y;

        float dxi = yi - xli; xli = yi;
        float av = fmaf(dxi, 1.0f / 6.0f, 0.5f * S1i);   // old S1i
        float bv = fmaf(dxi, 0.5f, S1i);
        S1i += dxi;
        u64 a2 = pack2(av, av);
        u64 b2 = pack2(bv, bv);

        u64 dj01 = hib ? d2 : d0;
        u64 dj23 = hib ? d3 : d1;

        u64 m01 = fma2(a2, dj01, S2p0);                  // old S2
        u64 m23 = fma2(a2, dj23, S2p1);
        S2p0 = fma2(b2, dj01, S2p0);
        S2p1 = fma2(b2, dj23, S2p1);

        float m0, m1, m2, m3;
        unpack2(m01, m0, m1); unpack2(m23, m2, m3);
        u64 MM[4] = { pack2(m0, m0), pack2(m1, m1), pack2(m2, m2), pack2(m3, m3) };
        u64 dd[4] = { d0, d1, d2, d3 };
#pragma unroll
        for (int q = 0; q < 4; ++q)
#pragma unroll
            for (int kp = 0; kp < 4; ++kp)
                S3p[q][kp] = fma2(MM[q], dd[kp], S3p[q][kp]);
    }

    // ---- unpack scan state to scalars ----
    float S3f[4][8];
#pragma unroll
    for (int q = 0; q < 4; ++q)
#pragma unroll
        for (int kp = 0; kp < 4; ++kp)
            unpack2(S3p[q][kp], S3f[q][2 * kp], S3f[q][2 * kp + 1]);
    float S2f[4];
    unpack2(S2p0, S2f[0], S2f[1]);
    unpack2(S2p1, S2f[2], S2f[3]);
    float S1f[8];
    {
        u64 q0 = fma2(x00, NEG1, xp0); unpack2(q0, S1f[0], S1f[1]);
        u64 q1 = fma2(x01, NEG1, xp1); unpack2(q1, S1f[2], S1f[3]);
        u64 q2 = fma2(x02, NEG1, xp2); unpack2(q2, S1f[4], S1f[5]);
        u64 q3 = fma2(x03, NEG1, xp3); unpack2(q3, S1f[6], S1f[7]);
    }

    // ---------------- Chen tree-combine via shared memory ----------------
    __shared__ float sig[BPB][4][SIGSZ];

    auto store_sig = [&](float* p) {
        if (s == 0) {
#pragma unroll
            for (int k = 0; k < 8; ++k) p[k] = S1f[k];
        }
#pragma unroll
        for (int q = 0; q < 4; ++q)
            p[8 + i * 9 + jb + q] = S2f[q];
#pragma unroll
        for (int q = 0; q < 4; ++q)
#pragma unroll
            for (int k = 0; k < 8; ++k)
                p[80 + (i * 8 + jb + q) * 9 + k] = S3f[q][k];
    };

    auto combine = [&](const float* p) {   // regs = earlier part a, p = later part b
        float S1b[8];
#pragma unroll
        for (int k = 0; k < 8; ++k) S1b[k] = p[k];
#pragma unroll
        for (int q = 0; q < 4; ++q) {
            const float* s2row = p + 8 + (jb + q) * 9;            // S2b[j,:]
            const float* s3row = p + 80 + (i * 8 + jb + q) * 9;   // S3b[i,j,:]
#pragma unroll
            for (int k = 0; k < 8; ++k)
                S3f[q][k] += S2f[q] * S1b[k] + S1i * s2row[k] + s3row[k];
            float S1bj = hib ? S1b[4 + q] : S1b[q];
            S2f[q] += S1i * S1bj + p[8 + i * 9 + jb + q];
        }
#pragma unroll
        for (int k = 0; k < 8; ++k) S1f[k] += S1b[k];
        S1i += p[i];
    };

    if (chunk == 1 || chunk == 3) store_sig(&sig[bL][chunk][0]);
    __syncthreads();
    if (chunk == 0) {
        combine(&sig[bL][1][0]);
    } else if (chunk == 2) {
        combine(&sig[bL][3][0]);
        store_sig(&sig[bL][2][0]);
    }
    __syncthreads();
    if (chunk != 0) return;          // chunk-0 groups are always lanes 0-15

    combine(&sig[bL][2][0]);

    // ---------------- log projection + writeback ----------------
    float* p0 = &sig[bL][0][0];
#pragma unroll
    for (int q = 0; q < 4; ++q)
        p0[8 + i * 9 + jb + q] = S2f[q];   // publish full S2 for [j,k] reads
    __syncwarp(0x0000FFFFu);

    float* ob = out + (size_t)b * OUT_PB;

    // l1
    if (s == 0) {
        *reinterpret_cast<float4*>(ob)     = make_float4(S1f[0], S1f[1], S1f[2], S1f[3]);
        *reinterpret_cast<float4*>(ob + 4) = make_float4(S1f[4], S1f[5], S1f[6], S1f[7]);
    }

    // l2 = S2 - 0.5 S1 x S1
    {
        float4 v; float* vv = &v.x;
#pragma unroll
        for (int q = 0; q < 4; ++q) {
            float S1j = hib ? S1f[4 + q] : S1f[q];
            vv[q] = S2f[q] - 0.5f * S1i * S1j;
        }
        *reinterpret_cast<float4*>(ob + 8 + 4 * s) = v;
    }

    // l3 = S3 - 0.5 (S1_i S2[j,k] + S2[i,j] S1_k) + (1/3) S1_i S1_j S1_k
#pragma unroll
    for (int q = 0; q < 4; ++q) {
        float S1j  = hib ? S1f[4 + q] : S1f[q];
        float S2ij = S2f[q];
        float tij  = (1.0f / 3.0f) * S1i * S1j;
        const float* row = p0 + 8 + (jb + q) * 9;    // S2[j,:]
        float4 lo, hi4;
        float* lv = &lo.x; float* hv = &hi4.x;
#pragma unroll
        for (int k = 0; k < 8; ++k) {
            float val = S3f[q][k]
                      - 0.5f * (S1i * row[k] + S2ij * S1f[k])
                      + tij * S1f[k];
            if (k < 4) lv[k] = val; else hv[k - 4] = val;
        }
        float* dst = ob + 72 + 32 * s + 8 * q;
        *reinterpret_cast<float4*>(dst)     = lo;
        *reinterpret_cast<float4*>(dst + 4) = hi4;
    }
}

extern "C" void kernel_launch(void* const* d_in, const int* in_sizes, int n_in,
                              void* d_out, int out_size)
{
    const float* x = (const float*)d_in[0];
    float* out = (float*)d_out;
    (void)in_sizes; (void)n_in; (void)out_size;

    const int blocks = BATCH / BPB;   // 512
    logsig_kernel<<<blocks, TPB>>>(x, out);
}